// round 1
// baseline (speedup 1.0000x reference)
#include <cuda_runtime.h>
#include <cstdint>

// AdjustableModePooling:
//   x: (64, 65536, 10) f32 of integer labels 0..9, flat-viewed as (B=64, C=10, D=65536)
//   window K1=8 along D, mode per window (ties -> smallest value)
//   out flat index = c*(8192*64) + j*64 + b   (out_size = 5,242,880 f32)
//
// Per thread: 4 consecutive windows of one (b,c) row -> 128B contiguous read.
// b lives in the low 6 bits of the thread id -> warp stores are 128B coalesced.

static constexpr unsigned B = 64;
static constexpr unsigned C = 10;
static constexpr unsigned D = 65536;
static constexpr unsigned NJ = 8192;          // (D-8)/8+1
static constexpr unsigned JG = NJ / 4;        // 2048 j-groups of 4 windows

__global__ __launch_bounds__(256, 8)
void mode_pool_kernel(const float* __restrict__ x, float* __restrict__ out)
{
    unsigned T = blockIdx.x * 256u + threadIdx.x;
    unsigned b    = T & 63u;
    unsigned rest = T >> 6;
    unsigned jg   = rest & (JG - 1u);
    unsigned c    = rest >> 11;               // 0..9, grid exactly covers domain

    // input: 4 windows * 8 floats = 32 floats = 8 float4, contiguous, 32B-aligned
    const float4* p = reinterpret_cast<const float4*>(
        x + (size_t)b * (C * D) + (size_t)c * D + (size_t)jg * 32u);

    float4 v[8];
#pragma unroll
    for (int i = 0; i < 8; i++) v[i] = p[i];

    float* ob = out + (size_t)c * (NJ * B) + (size_t)jg * (4u * B) + b;

#pragma unroll
    for (int w = 0; w < 4; w++) {
        float f0 = v[2*w].x,   f1 = v[2*w].y,   f2 = v[2*w].z,   f3 = v[2*w].w;
        float f4 = v[2*w+1].x, f5 = v[2*w+1].y, f6 = v[2*w+1].z, f7 = v[2*w+1].w;

        // nibble histogram: value v -> nibble 4v of a 64-bit accumulator.
        // magic add 2^23 puts the integer in the low mantissa bits (exact for 0..9).
        unsigned long long acc = 0ull;
        {
            unsigned u;
            u = __float_as_uint(f0 + 8388608.0f); acc += 1ull << ((u & 15u) * 4u);
            u = __float_as_uint(f1 + 8388608.0f); acc += 1ull << ((u & 15u) * 4u);
            u = __float_as_uint(f2 + 8388608.0f); acc += 1ull << ((u & 15u) * 4u);
            u = __float_as_uint(f3 + 8388608.0f); acc += 1ull << ((u & 15u) * 4u);
            u = __float_as_uint(f4 + 8388608.0f); acc += 1ull << ((u & 15u) * 4u);
            u = __float_as_uint(f5 + 8388608.0f); acc += 1ull << ((u & 15u) * 4u);
            u = __float_as_uint(f6 + 8388608.0f); acc += 1ull << ((u & 15u) * 4u);
            u = __float_as_uint(f7 + 8388608.0f); acc += 1ull << ((u & 15u) * 4u);
        }

        unsigned lo = (unsigned)acc;
        unsigned hi = (unsigned)(acc >> 32);

        // argmax over 10 bins, tie -> smallest value:
        // key = (count << 4) | (15 - value); max key wins; mode = 15 - (key & 15).
        unsigned best = 0u;
#pragma unroll
        for (unsigned vv = 0; vv < 10; vv++) {
            unsigned nib = (vv < 8) ? ((lo >> (4u * vv)) & 15u)
                                    : ((hi >> (4u * (vv - 8u))) & 15u);
            unsigned key = (nib << 4) | (15u - vv);
            best = best > key ? best : key;
        }

        ob[w * B] = (float)(15u - (best & 15u));
    }
}

extern "C" void kernel_launch(void* const* d_in, const int* in_sizes, int n_in,
                              void* d_out, int out_size)
{
    const float* x = (const float*)d_in[0];
    float* out = (float*)d_out;
    // total threads = B * JG * C = 64 * 2048 * 10 = 1,310,720 -> 5120 blocks of 256
    unsigned total = B * JG * C;
    mode_pool_kernel<<<total / 256, 256>>>(x, out);
}

// round 3
// speedup vs baseline: 1.3053x; 1.3053x over previous
#include <cuda_runtime.h>
#include <cstdint>

// AdjustableModePooling:
//   x: (64, 65536, 10) f32 of integer labels 0..9, flat-viewed as (B=64, C=10, D=65536)
//   window K1=8 along D, mode per window (ties -> smallest value)
//   out flat index = c*(8192*64) + j*64 + b
//
// Layout: warp = one (b,c) row segment, lane = one window (32B).
// Lane l loads LDG.128 at 32l and 32l+16 -> 8 lines per LDG (16 wf/KB vs 64 before).
// Output transposed through smem so stores hit 4 lines per STG.32 (32B sectors).

static constexpr unsigned B  = 64;
static constexpr unsigned C  = 10;
static constexpr unsigned D  = 65536;
static constexpr unsigned NJ = 8192;     // (D-8)/8+1
static constexpr unsigned JT = 128;      // windows per block tile (per row)
static constexpr unsigned RT = 8;        // rows (b values) per block = warps per block

__device__ __forceinline__ unsigned long long hist4(float a, float b_, float c_, float d_)
{
    // magic add 2^23: integer 0..9 lands in low mantissa bits, u&15 == value
    unsigned long long h = 0ull;
    unsigned u;
    u = __float_as_uint(a  + 8388608.0f); h += 1ull << ((u & 15u) * 4u);
    u = __float_as_uint(b_ + 8388608.0f); h += 1ull << ((u & 15u) * 4u);
    u = __float_as_uint(c_ + 8388608.0f); h += 1ull << ((u & 15u) * 4u);
    u = __float_as_uint(d_ + 8388608.0f); h += 1ull << ((u & 15u) * 4u);
    return h;
}

__device__ __forceinline__ unsigned kmax(unsigned a, unsigned b) { return a > b ? a : b; }

__device__ __forceinline__ float window_mode(float4 v0, float4 v1)
{
    // two independent accumulation chains, then combine
    unsigned long long acc = hist4(v0.x, v0.y, v0.z, v0.w)
                           + hist4(v1.x, v1.y, v1.z, v1.w);
    unsigned lo = (unsigned)acc;
    unsigned hi = (unsigned)(acc >> 32);

    // key_v = (count_v << 4) | (15 - v); max key wins; tie -> smallest v.
    // Each key is one shift + one LOP3((t & 0xF0) | tie).
    unsigned k0 = ((lo << 4)  & 0xF0u) | 15u;
    unsigned k1 = ( lo        & 0xF0u) | 14u;
    unsigned k2 = ((lo >> 4)  & 0xF0u) | 13u;
    unsigned k3 = ((lo >> 8)  & 0xF0u) | 12u;
    unsigned k4 = ((lo >> 12) & 0xF0u) | 11u;
    unsigned k5 = ((lo >> 16) & 0xF0u) | 10u;
    unsigned k6 = ((lo >> 20) & 0xF0u) |  9u;
    unsigned k7 = ((lo >> 24) & 0xF0u) |  8u;
    unsigned k8 = ((hi << 4)  & 0xF0u) |  7u;
    unsigned k9 = ( hi        & 0xF0u) |  6u;

    unsigned m = kmax(kmax(kmax(k0, k1), kmax(k2, k3)),
                      kmax(kmax(k4, k5), kmax(k6, k7)));
    m = kmax(m, kmax(k8, k9));
    return (float)(15u - (m & 15u));
}

__global__ __launch_bounds__(256, 5)
void mode_pool_kernel(const float* __restrict__ x, float* __restrict__ out)
{
    __shared__ float s_out[JT * 9];          // [j_local][row], stride 9 -> no bank conflicts

    unsigned g  = blockIdx.x;
    unsigned jt = g & 63u;                   // 64 j-tiles of 128 windows
    unsigned bg = (g >> 6) & 7u;             // 8 groups of 8 b-rows
    unsigned c  = g >> 9;                    // 0..9

    unsigned w = threadIdx.x >> 5;           // warp -> row within group
    unsigned l = threadIdx.x & 31u;          // lane -> window within 32-window chunk
    unsigned b = bg * RT + w;

    const float4* rp = reinterpret_cast<const float4*>(
        x + (size_t)b * (C * D) + (size_t)c * D + (size_t)jt * (JT * 8u));

    // 4 chunks of 32 windows; lane l's window in chunk it = float4s (it*64 + 2l, +1).
    // Issue all 8 loads up front for MLP.
    float4 v[8];
#pragma unroll
    for (int it = 0; it < 4; it++) {
        v[2 * it]     = rp[it * 64 + 2 * l];
        v[2 * it + 1] = rp[it * 64 + 2 * l + 1];
    }

#pragma unroll
    for (int it = 0; it < 4; it++) {
        float m = window_mode(v[2 * it], v[2 * it + 1]);
        s_out[(it * 32u + l) * 9u + w] = m;  // banks (9*l + w) % 32 -> conflict-free
    }
    __syncthreads();

    // Store phase: thread t -> (j = t>>3 (+32r), b_off = t&7); each STG.32 hits 4 lines,
    // 32B-aligned sectors (bg*8 is a multiple of 8 floats).
    float* ob = out + (size_t)c * (NJ * B) + (size_t)(jt * JT) * B + (size_t)bg * RT;
    unsigned bo = threadIdx.x & 7u;
    unsigned j0 = threadIdx.x >> 3;          // 0..31
#pragma unroll
    for (int r = 0; r < 4; r++) {
        unsigned j = j0 + 32u * r;
        ob[(size_t)j * B + bo] = s_out[j * 9u + bo];
    }
}

extern "C" void kernel_launch(void* const* d_in, const int* in_sizes, int n_in,
                              void* d_out, int out_size)
{
    const float* x = (const float*)d_in[0];
    float* out = (float*)d_out;
    // blocks = 64 j-tiles * 8 b-groups * 10 c = 5120
    mode_pool_kernel<<<5120, 256>>>(x, out);
}

// round 4
// speedup vs baseline: 1.3066x; 1.0010x over previous
#include <cuda_runtime.h>
#include <cstdint>

// AdjustableModePooling:
//   x: (64, 65536, 10) f32 of integer labels 0..9, flat-viewed as (B=64, C=10, D=65536)
//   window K1=8 along D, mode per window (ties -> smallest value)
//   out flat index = c*(8192*64) + j*64 + b
//
// R4: 2 windows/thread (was 4) -> ~16 fewer live regs -> occupancy 56.8% -> ~85%.
// Lane = window along D (R3 win: 8 lines per LDG.128). Smem transpose for stores.
// Final int->float via exponent-magic (LOP3+FADD) instead of I2F.

static constexpr unsigned B  = 64;
static constexpr unsigned C  = 10;
static constexpr unsigned D  = 65536;
static constexpr unsigned NJ = 8192;     // (D-8)/8+1
static constexpr unsigned JT = 64;       // windows per block tile (per row)
static constexpr unsigned RT = 8;        // rows (b values) per block = warps per block

__device__ __forceinline__ unsigned long long hist4(float a, float b_, float c_, float d_)
{
    // magic add 2^23: integer 0..9 lands in low mantissa bits, u&15 == value
    unsigned long long h = 0ull;
    unsigned u;
    u = __float_as_uint(a  + 8388608.0f); h += 1ull << ((u & 15u) * 4u);
    u = __float_as_uint(b_ + 8388608.0f); h += 1ull << ((u & 15u) * 4u);
    u = __float_as_uint(c_ + 8388608.0f); h += 1ull << ((u & 15u) * 4u);
    u = __float_as_uint(d_ + 8388608.0f); h += 1ull << ((u & 15u) * 4u);
    return h;
}

__device__ __forceinline__ unsigned kmax(unsigned a, unsigned b) { return a > b ? a : b; }

__device__ __forceinline__ float window_mode(float4 v0, float4 v1)
{
    unsigned long long acc = hist4(v0.x, v0.y, v0.z, v0.w)
                           + hist4(v1.x, v1.y, v1.z, v1.w);
    unsigned lo = (unsigned)acc;
    unsigned hi = (unsigned)(acc >> 32);

    // key_v = (count_v << 4) | (15 - v); max key wins; tie -> smallest v.
    unsigned k0 = ((lo << 4)  & 0xF0u) | 15u;
    unsigned k1 = ( lo        & 0xF0u) | 14u;
    unsigned k2 = ((lo >> 4)  & 0xF0u) | 13u;
    unsigned k3 = ((lo >> 8)  & 0xF0u) | 12u;
    unsigned k4 = ((lo >> 12) & 0xF0u) | 11u;
    unsigned k5 = ((lo >> 16) & 0xF0u) | 10u;
    unsigned k6 = ((lo >> 20) & 0xF0u) |  9u;
    unsigned k7 = ((lo >> 24) & 0xF0u) |  8u;
    unsigned k8 = ((hi << 4)  & 0xF0u) |  7u;
    unsigned k9 = ( hi        & 0xF0u) |  6u;

    unsigned m = kmax(kmax(kmax(k0, k1), kmax(k2, k3)),
                      kmax(kmax(k4, k5), kmax(k6, k7)));
    m = kmax(m, kmax(k8, k9));

    // mode = 15 - (m & 15) = (~m) & 15 ; int->float via exponent magic (no I2F):
    unsigned r = (~m) & 15u;
    return __uint_as_float(0x4B000000u | r) - 8388608.0f;
}

__global__ __launch_bounds__(256, 7)
void mode_pool_kernel(const float* __restrict__ x, float* __restrict__ out)
{
    __shared__ float s_out[JT * 9];          // [j_local][row], stride 9 -> no bank conflicts

    unsigned g  = blockIdx.x;
    unsigned jt = g & 127u;                  // 128 j-tiles of 64 windows
    unsigned bg = (g >> 7) & 7u;             // 8 groups of 8 b-rows
    unsigned c  = g >> 10;                   // 0..9

    unsigned w = threadIdx.x >> 5;           // warp -> row within group
    unsigned l = threadIdx.x & 31u;          // lane -> window within 32-window chunk
    unsigned b = bg * RT + w;

    const float4* rp = reinterpret_cast<const float4*>(
        x + (size_t)b * (C * D) + (size_t)c * D + (size_t)jt * (JT * 8u));

    // 2 chunks of 32 windows; lane l's window in chunk it = float4s (it*64 + 2l, +1).
    // All 4 loads issued up front (64B in flight per thread); streaming hint.
    float4 v[4];
#pragma unroll
    for (int it = 0; it < 2; it++) {
        v[2 * it]     = __ldcs(&rp[it * 64 + 2 * l]);
        v[2 * it + 1] = __ldcs(&rp[it * 64 + 2 * l + 1]);
    }

#pragma unroll
    for (int it = 0; it < 2; it++) {
        float m = window_mode(v[2 * it], v[2 * it + 1]);
        s_out[(it * 32u + l) * 9u + w] = m;  // banks (9*l + w) % 32 -> conflict-free
    }
    __syncthreads();

    // Store phase: thread t -> (j = t>>3 (+32r), b_off = t&7); each warp's STG.32s
    // hit 4 lines with full 32B sectors (bg*8 floats = 32B aligned).
    float* ob = out + (size_t)c * (NJ * B) + (size_t)(jt * JT) * B + (size_t)bg * RT;
    unsigned bo = threadIdx.x & 7u;
    unsigned j0 = threadIdx.x >> 3;          // 0..31
#pragma unroll
    for (int r = 0; r < 2; r++) {
        unsigned j = j0 + 32u * r;
        __stcs(&ob[(size_t)j * B + bo], s_out[j * 9u + bo]);
    }
}

extern "C" void kernel_launch(void* const* d_in, const int* in_sizes, int n_in,
                              void* d_out, int out_size)
{
    const float* x = (const float*)d_in[0];
    float* out = (float*)d_out;
    // blocks = 128 j-tiles * 8 b-groups * 10 c = 10240
    mode_pool_kernel<<<10240, 256>>>(x, out);
}

// round 5
// speedup vs baseline: 1.3167x; 1.0077x over previous
#include <cuda_runtime.h>
#include <cstdint>

// AdjustableModePooling:
//   x: (64, 65536, 10) f32 of integer labels 0..9, flat-viewed as (B=64, C=10, D=65536)
//   window K1=8 along D, mode per window (ties -> smallest value)
//   out flat index = c*(8192*64) + j*64 + b
//
// R5: ALU diet. DRAM (72%) and alu (61%) co-saturate; cut hist+argmax instrs:
//  - u = bits(fma(f,4,2^23)) = 0x4B000000|4v  -> shift amount is u&63 directly
//  - packed byte keys + __vmaxu4 fold for the argmax (tie -> smallest value)

static constexpr unsigned B  = 64;
static constexpr unsigned C  = 10;
static constexpr unsigned D  = 65536;
static constexpr unsigned NJ = 8192;     // (D-8)/8+1
static constexpr unsigned JT = 64;       // windows per block tile (per row)
static constexpr unsigned RT = 8;        // rows (b values) per block = warps per block

__device__ __forceinline__ unsigned kmax(unsigned a, unsigned b) { return a > b ? a : b; }

__device__ __forceinline__ unsigned long long hist4(float a, float b_, float c_, float d_)
{
    // fma(f,4,2^23): bits = 0x4B000000 | 4v (exact for v in 0..9).
    // (bits & 63) == 4v  ->  nibble v of the 64-bit histogram.
    unsigned long long h = 0ull;
    h += 1ull << (__float_as_uint(__fmaf_rn(a,  4.0f, 8388608.0f)) & 63u);
    h += 1ull << (__float_as_uint(__fmaf_rn(b_, 4.0f, 8388608.0f)) & 63u);
    h += 1ull << (__float_as_uint(__fmaf_rn(c_, 4.0f, 8388608.0f)) & 63u);
    h += 1ull << (__float_as_uint(__fmaf_rn(d_, 4.0f, 8388608.0f)) & 63u);
    return h;
}

__device__ __forceinline__ float window_mode(float4 v0, float4 v1)
{
    // two independent accumulation chains, combined once
    unsigned long long acc = hist4(v0.x, v0.y, v0.z, v0.w)
                           + hist4(v1.x, v1.y, v1.z, v1.w);
    unsigned lo = (unsigned)acc;          // counts of v=0..7, nibble v
    unsigned hi = (unsigned)(acc >> 32);  // counts of v=8 (nib0), v=9 (nib1)

    // key_v = (count_v << 4) | (15 - v); max key wins; tie -> smallest v.
    // Even v (0,2,4,6) and odd v (1,3,5,7) keys built 4-at-a-time as bytes:
    unsigned E = ((lo << 4) & 0xF0F0F0F0u) | 0x090B0D0Fu;  // bytes: v=0,2,4,6
    unsigned O = ( lo       & 0xF0F0F0F0u) | 0x080A0C0Eu;  // bytes: v=1,3,5,7

    unsigned M = __vmaxu4(E, O);
    M = __vmaxu4(M, M >> 16);
    M = __vmaxu4(M, M >> 8);              // byte0 = max of the 8 low-bin keys

    unsigned k8 = ((hi << 4) & 0xF0u) | 7u;
    unsigned k9 = ( hi       & 0xF0u) | 6u;
    unsigned best = kmax(M & 0xFFu, kmax(k8, k9));

    // mode = 15 - (best & 15) = (~best) & 15 ; int->float via exponent magic
    unsigned r = (~best) & 15u;
    return __uint_as_float(0x4B000000u | r) - 8388608.0f;
}

__global__ __launch_bounds__(256, 7)
void mode_pool_kernel(const float* __restrict__ x, float* __restrict__ out)
{
    __shared__ float s_out[JT * 9];          // [j_local][row], stride 9 -> no bank conflicts

    unsigned g  = blockIdx.x;
    unsigned jt = g & 127u;                  // 128 j-tiles of 64 windows
    unsigned bg = (g >> 7) & 7u;             // 8 groups of 8 b-rows
    unsigned c  = g >> 10;                   // 0..9

    unsigned w = threadIdx.x >> 5;           // warp -> row within group
    unsigned l = threadIdx.x & 31u;          // lane -> window within 32-window chunk
    unsigned b = bg * RT + w;

    const float4* rp = reinterpret_cast<const float4*>(
        x + (size_t)b * (C * D) + (size_t)c * D + (size_t)jt * (JT * 8u));

    // 2 chunks of 32 windows; lane l's window in chunk it = float4s (it*64 + 2l, +1).
    float4 v[4];
#pragma unroll
    for (int it = 0; it < 2; it++) {
        v[2 * it]     = __ldcs(&rp[it * 64 + 2 * l]);
        v[2 * it + 1] = __ldcs(&rp[it * 64 + 2 * l + 1]);
    }

#pragma unroll
    for (int it = 0; it < 2; it++) {
        float m = window_mode(v[2 * it], v[2 * it + 1]);
        s_out[(it * 32u + l) * 9u + w] = m;  // banks (9*l + w) % 32 -> conflict-free
    }
    __syncthreads();

    // Store phase: thread t -> (j = t>>3 (+32r), b_off = t&7); warp STG.32s hit
    // 4 lines with full 32B sectors (bg*8 floats = 32B aligned).
    float* ob = out + (size_t)c * (NJ * B) + (size_t)(jt * JT) * B + (size_t)bg * RT;
    unsigned bo = threadIdx.x & 7u;
    unsigned j0 = threadIdx.x >> 3;          // 0..31
#pragma unroll
    for (int r = 0; r < 2; r++) {
        unsigned j = j0 + 32u * r;
        __stcs(&ob[(size_t)j * B + bo], s_out[j * 9u + bo]);
    }
}

extern "C" void kernel_launch(void* const* d_in, const int* in_sizes, int n_in,
                              void* d_out, int out_size)
{
    const float* x = (const float*)d_in[0];
    float* out = (float*)d_out;
    // blocks = 128 j-tiles * 8 b-groups * 10 c = 10240
    mode_pool_kernel<<<10240, 256>>>(x, out);
}